// round 4
// baseline (speedup 1.0000x reference)
#include <cuda_runtime.h>
#include <cuda_bf16.h>
#include <cstdint>

// Problem constants (match reference setup_inputs)
#define NN 40000
#define EE 640000
#define GG 64
#define DD 128          // D_IN = D_EMB = D_HID
#define DOUT 36

// ---------------- scratch (device globals; no allocation allowed) -----------
__device__ __align__(16) float g_deg[NN];          // degree, then rsqrt in place
__device__ __align__(16) float g_hW[(size_t)NN * DD];
__device__ __align__(16) float g_agg[(size_t)NN * DD];
__device__ __align__(16) int   g_pmaxi[GG * DD];   // float bits, values >= 0
__device__ __align__(16) float g_psum[GG * DD];
__device__ float g_cnt[GG];

// ---------------- helpers ---------------------------------------------------
__device__ __forceinline__ void red_add_v4(float* p, float a, float b, float c, float d) {
    asm volatile("red.global.add.v4.f32 [%0], {%1, %2, %3, %4};"
                 :: "l"(p), "f"(a), "f"(b), "f"(c), "f"(d) : "memory");
}
__device__ __forceinline__ void red_add_f32(float* p, float v) {
    asm volatile("red.global.add.f32 [%0], %1;" :: "l"(p), "f"(v) : "memory");
}

// ---------------- kernels ---------------------------------------------------

// zero the big accumulator (40000*128 floats) as float4
__global__ void k_zero_agg() {
    float4 z = make_float4(0.f, 0.f, 0.f, 0.f);
    float4* p = reinterpret_cast<float4*>(g_agg);
    int n = NN * (DD / 4);
    for (int i = blockIdx.x * blockDim.x + threadIdx.x; i < n; i += gridDim.x * blockDim.x)
        p[i] = z;
}

// small-state init: deg=1 (self loop), pooled max/sum = 0, cnt = 0
__global__ void k_init_small() {
    int i = blockIdx.x * blockDim.x + threadIdx.x;
    if (i < NN) g_deg[i] = 1.0f;
    if (i < GG * DD) { g_pmaxi[i] = 0; g_psum[i] = 0.0f; }
    if (i < GG) g_cnt[i] = 0.0f;
}

// deg[dst] += edge_weight
__global__ void k_deg(const int* __restrict__ ei, const float* __restrict__ ew) {
    int e = blockIdx.x * blockDim.x + threadIdx.x;
    if (e >= EE) return;
    red_add_f32(&g_deg[ei[EE + e]], ew[e]);
}

// deg -> rsqrt(deg) in place (deg >= 1 always)
__global__ void k_dinv() {
    int n = blockIdx.x * blockDim.x + threadIdx.x;
    if (n < NN) g_deg[n] = rsqrtf(g_deg[n]);
}

// hW = x @ conv_w  (40000x128 @ 128x128, fp32)
// block: 256 threads computes 64 rows x 128 cols, full K=128 resident in smem.
// dynamic smem: Ws[128*128] + xs[64*132] = 99328 B
__global__ void k_gemm(const float* __restrict__ X, const float* __restrict__ W) {
    extern __shared__ float smem[];
    float* Ws = smem;                   // 128 x 128
    float* xs = smem + 128 * 128;       // 64 x 132 (padded)

    const int tid = threadIdx.x;
    const int row0 = blockIdx.x * 64;

    // load W (4096 float4)
    {
        const float4* Wg = reinterpret_cast<const float4*>(W);
        float4* Ws4 = reinterpret_cast<float4*>(Ws);
        #pragma unroll
        for (int i = 0; i < 16; i++) Ws4[tid + i * 256] = Wg[tid + i * 256];
    }
    // load x tile (2048 float4), padded row stride 132
    {
        const float4* Xg = reinterpret_cast<const float4*>(X + (size_t)row0 * DD);
        #pragma unroll
        for (int i = 0; i < 8; i++) {
            int idx = tid + i * 256;
            int r = idx >> 5, kq = idx & 31;
            reinterpret_cast<float4*>(xs + r * 132)[kq] = Xg[idx];
        }
    }
    __syncthreads();

    const int lane = tid & 31;
    const int wrp = tid >> 5;           // 0..7, each warp: 8 rows
    const float* xrow = xs + (wrp * 8) * 132;

    float acc[8][4];
    #pragma unroll
    for (int j = 0; j < 8; j++) { acc[j][0] = acc[j][1] = acc[j][2] = acc[j][3] = 0.f; }

    #pragma unroll 8
    for (int k = 0; k < 128; k++) {
        float4 w4 = reinterpret_cast<const float4*>(Ws + k * 128)[lane];
        #pragma unroll
        for (int j = 0; j < 8; j++) {
            float xv = xrow[j * 132 + k];
            acc[j][0] = fmaf(xv, w4.x, acc[j][0]);
            acc[j][1] = fmaf(xv, w4.y, acc[j][1]);
            acc[j][2] = fmaf(xv, w4.z, acc[j][2]);
            acc[j][3] = fmaf(xv, w4.w, acc[j][3]);
        }
    }

    #pragma unroll
    for (int j = 0; j < 8; j++) {
        int row = row0 + wrp * 8 + j;
        reinterpret_cast<float4*>(g_hW + (size_t)row * DD)[lane] =
            make_float4(acc[j][0], acc[j][1], acc[j][2], acc[j][3]);
    }
}

// one warp per edge: agg[dst] += hW[src] * (dinv[src]*w*dinv[dst])
__global__ void k_scatter(const int* __restrict__ ei, const float* __restrict__ ew) {
    int gw = (blockIdx.x * blockDim.x + threadIdx.x) >> 5;
    if (gw >= EE) return;
    const int lane = threadIdx.x & 31;

    int src = ei[gw];
    int dst = ei[EE + gw];
    float norm = g_deg[src] * ew[gw] * g_deg[dst];

    float4 v = reinterpret_cast<const float4*>(g_hW + (size_t)src * DD)[lane];
    float* ap = g_agg + (size_t)dst * DD + lane * 4;
    red_add_v4(ap, v.x * norm, v.y * norm, v.z * norm, v.w * norm);
}

// finalize node features (+self loop, +bias, relu) and pool per graph
// one warp per node
__global__ void k_pool(const float* __restrict__ bias, const int* __restrict__ batchv) {
    int n = (blockIdx.x * blockDim.x + threadIdx.x) >> 5;
    if (n >= NN) return;
    const int lane = threadIdx.x & 31;

    float dn = g_deg[n];
    float sl = dn * dn;                 // self-loop norm
    float4 a = reinterpret_cast<const float4*>(g_agg + (size_t)n * DD)[lane];
    float4 h = reinterpret_cast<const float4*>(g_hW + (size_t)n * DD)[lane];
    float4 b = reinterpret_cast<const float4*>(bias)[lane];

    float v0 = fmaxf(a.x + h.x * sl + b.x, 0.f);
    float v1 = fmaxf(a.y + h.y * sl + b.y, 0.f);
    float v2 = fmaxf(a.z + h.z * sl + b.z, 0.f);
    float v3 = fmaxf(a.w + h.w * sl + b.w, 0.f);

    int g = batchv[n];
    int base = g * DD + lane * 4;
    // post-relu values are >= 0 -> int-ordered max is float max, init 0 is correct
    atomicMax(&g_pmaxi[base + 0], __float_as_int(v0));
    atomicMax(&g_pmaxi[base + 1], __float_as_int(v1));
    atomicMax(&g_pmaxi[base + 2], __float_as_int(v2));
    atomicMax(&g_pmaxi[base + 3], __float_as_int(v3));
    red_add_v4(&g_psum[base], v0, v1, v2, v3);
    if (lane == 0) red_add_f32(&g_cnt[g], 1.0f);
}

// per-graph MLP: one block (128 threads) per graph runs all three layers
__global__ void k_mlp(const float* __restrict__ rho,
                      const float* __restrict__ w1, const float* __restrict__ b1,
                      const float* __restrict__ w2, const float* __restrict__ b2,
                      const float* __restrict__ w3, const float* __restrict__ b3,
                      float* __restrict__ out) {
    __shared__ float hg[260];
    __shared__ float z1[DD];
    __shared__ float z2[DD];
    const int g = blockIdx.x;
    const int t = threadIdx.x;

    float cnt = g_cnt[g];
    float inv = 1.0f / fmaxf(cnt, 1.0f);
    hg[t] = __int_as_float(g_pmaxi[g * DD + t]);
    hg[DD + t] = g_psum[g * DD + t] * inv;
    if (t == 0) hg[2 * DD] = rho[g];
    __syncthreads();

    float acc = b1[t];
    #pragma unroll 8
    for (int k = 0; k < 2 * DD + 1; k++) acc = fmaf(hg[k], w1[k * DD + t], acc);
    z1[t] = fmaxf(acc, 0.f);
    __syncthreads();

    acc = b2[t];
    #pragma unroll 8
    for (int k = 0; k < DD; k++) acc = fmaf(z1[k], w2[k * DD + t], acc);
    z2[t] = fmaxf(acc, 0.f);
    __syncthreads();

    if (t < DOUT) {
        acc = b3[t];
        #pragma unroll 8
        for (int k = 0; k < DD; k++) acc = fmaf(z2[k], w3[k * DOUT + t], acc);
        out[g * DOUT + t] = acc;
    }
}

// ---------------- launch -----------------------------------------------------
extern "C" void kernel_launch(void* const* d_in, const int* in_sizes, int n_in,
                              void* d_out, int out_size) {
    const float* x      = (const float*)d_in[0];
    const float* ew     = (const float*)d_in[1];
    const float* rho    = (const float*)d_in[2];
    const float* conv_w = (const float*)d_in[3];
    const float* conv_b = (const float*)d_in[4];
    const float* w1     = (const float*)d_in[5];
    const float* b1     = (const float*)d_in[6];
    const float* w2     = (const float*)d_in[7];
    const float* b2     = (const float*)d_in[8];
    const float* w3     = (const float*)d_in[9];
    const float* b3     = (const float*)d_in[10];
    const int*   ei     = (const int*)d_in[11];
    const int*   batchv = (const int*)d_in[12];
    float* out = (float*)d_out;

    const int gemm_smem = (128 * 128 + 64 * 132) * 4;   // 99328 B
    cudaFuncSetAttribute(k_gemm, cudaFuncAttributeMaxDynamicSharedMemorySize, gemm_smem);

    // init
    k_zero_agg<<<5000, 256>>>();
    k_init_small<<<(NN + 255) / 256, 256>>>();

    // degree + normalization
    k_deg<<<(EE + 255) / 256, 256>>>(ei, ew);
    k_dinv<<<(NN + 255) / 256, 256>>>();

    // hW = x @ conv_w
    k_gemm<<<NN / 64, 256, gemm_smem>>>(x, conv_w);

    // edge scatter (one warp per edge)
    k_scatter<<<(EE * 32) / 256, 256>>>(ei, ew);

    // finalize + relu + pool (one warp per node)
    k_pool<<<(NN * 32) / 256, 256>>>(conv_b, batchv);

    // MLP head
    k_mlp<<<GG, DD>>>(rho, w1, b1, w2, b2, w3, b3, out);
}

// round 7
// speedup vs baseline: 1.9222x; 1.9222x over previous
#include <cuda_runtime.h>
#include <cuda_bf16.h>
#include <cstdint>

// Problem constants (match reference setup_inputs)
#define NN 40000
#define EE 640000
#define GG 64
#define DD 128          // D_IN = D_EMB = D_HID
#define DOUT 36
#define SCAN_BLK 1024
#define NSCAN ((NN + SCAN_BLK - 1) / SCAN_BLK)   // 40

// ---------------- scratch (device globals; no allocation allowed) -----------
__device__ __align__(16) float g_deg[NN];          // degree, then rsqrt in place
__device__ __align__(16) float g_hW[(size_t)NN * DD];
__device__ __align__(16) int   g_ecnt[NN];         // per-dst edge count
__device__ __align__(16) int   g_fill[NN];         // fill cursors
__device__ __align__(16) int   g_rs[NN];           // exclusive scan (per-block partial)
__device__ int   g_bsum[NSCAN];
__device__ int   g_boff[64];                       // scanned block offsets
__device__ __align__(16) int   g_csrc[EE];         // CSR: src node per slot
__device__ __align__(16) float g_cw[EE];           // CSR: normalized edge weight
__device__ __align__(16) int   g_pmaxi[GG * DD];   // float bits, values >= 0
__device__ __align__(16) float g_psum[GG * DD];
__device__ float g_cnt[GG];

// ---------------- helpers ---------------------------------------------------
__device__ __forceinline__ void red_add_v4(float* p, float a, float b, float c, float d) {
    asm volatile("red.global.add.v4.f32 [%0], {%1, %2, %3, %4};"
                 :: "l"(p), "f"(a), "f"(b), "f"(c), "f"(d) : "memory");
}
__device__ __forceinline__ void red_add_f32(float* p, float v) {
    asm volatile("red.global.add.f32 [%0], %1;" :: "l"(p), "f"(v) : "memory");
}
// row start with block offset folded in (avoids a 3rd scan pass)
__device__ __forceinline__ int row_start(int i) {
    return (i < NN) ? (g_rs[i] + g_boff[i >> 10]) : EE;
}

// ---------------- kernels ---------------------------------------------------

// reset all per-call state
__global__ void k_init() {
    int i = blockIdx.x * blockDim.x + threadIdx.x;
    if (i < NN) { g_deg[i] = 1.0f; g_ecnt[i] = 0; g_fill[i] = 0; }
    if (i < GG * DD) { g_pmaxi[i] = 0; g_psum[i] = 0.0f; }
    if (i < GG) g_cnt[i] = 0.0f;
}

// deg[dst] += edge_weight ; histogram counts per dst
__global__ void k_deg(const int* __restrict__ ei, const float* __restrict__ ew) {
    int e = blockIdx.x * blockDim.x + threadIdx.x;
    if (e >= EE) return;
    int dst = ei[EE + e];
    red_add_f32(&g_deg[dst], ew[e]);
    atomicAdd(&g_ecnt[dst], 1);
}

// per-block exclusive scan of counts + fused deg->rsqrt(deg)
__global__ void k_scan1() {
    __shared__ int s[SCAN_BLK];
    int t = threadIdx.x;
    int idx = blockIdx.x * SCAN_BLK + t;
    int c = (idx < NN) ? g_ecnt[idx] : 0;
    s[t] = c;
    __syncthreads();
    #pragma unroll
    for (int off = 1; off < SCAN_BLK; off <<= 1) {
        int v = (t >= off) ? s[t - off] : 0;
        __syncthreads();
        s[t] += v;
        __syncthreads();
    }
    if (idx < NN) g_rs[idx] = s[t] - c;         // exclusive within block
    if (t == SCAN_BLK - 1) g_bsum[blockIdx.x] = s[t];
    if (idx < NN) g_deg[idx] = rsqrtf(g_deg[idx]);
}

// scan the 40 block sums (single block, 64 threads)
__global__ void k_scan2() {
    __shared__ int s[64];
    int t = threadIdx.x;
    int c = (t < NSCAN) ? g_bsum[t] : 0;
    s[t] = c;
    __syncthreads();
    #pragma unroll
    for (int off = 1; off < 64; off <<= 1) {
        int v = (t >= off) ? s[t - off] : 0;
        __syncthreads();
        s[t] += v;
        __syncthreads();
    }
    g_boff[t] = s[t] - c;                       // exclusive
}

// scatter edges into CSR slots with precomputed symmetric norm
__global__ void k_fill(const int* __restrict__ ei, const float* __restrict__ ew) {
    int e = blockIdx.x * blockDim.x + threadIdx.x;
    if (e >= EE) return;
    int src = ei[e];
    int dst = ei[EE + e];
    float nrm = g_deg[src] * ew[e] * g_deg[dst];
    int pos = row_start(dst) + atomicAdd(&g_fill[dst], 1);
    g_csrc[pos] = src;
    g_cw[pos] = nrm;
}

// hW = x @ conv_w  (40000x128 @ 128x128, fp32)
__global__ void k_gemm(const float* __restrict__ X, const float* __restrict__ W) {
    extern __shared__ float smem[];
    float* Ws = smem;                   // 128 x 128
    float* xs = smem + 128 * 128;       // 64 x 132 (padded)

    const int tid = threadIdx.x;
    const int row0 = blockIdx.x * 64;

    {
        const float4* Wg = reinterpret_cast<const float4*>(W);
        float4* Ws4 = reinterpret_cast<float4*>(Ws);
        #pragma unroll
        for (int i = 0; i < 16; i++) Ws4[tid + i * 256] = Wg[tid + i * 256];
    }
    {
        const float4* Xg = reinterpret_cast<const float4*>(X + (size_t)row0 * DD);
        #pragma unroll
        for (int i = 0; i < 8; i++) {
            int idx = tid + i * 256;
            int r = idx >> 5, kq = idx & 31;
            reinterpret_cast<float4*>(xs + r * 132)[kq] = Xg[idx];
        }
    }
    __syncthreads();

    const int lane = tid & 31;
    const int wrp = tid >> 5;
    const float* xrow = xs + (wrp * 8) * 132;

    float acc[8][4];
    #pragma unroll
    for (int j = 0; j < 8; j++) { acc[j][0] = acc[j][1] = acc[j][2] = acc[j][3] = 0.f; }

    #pragma unroll 8
    for (int k = 0; k < 128; k++) {
        float4 w4 = reinterpret_cast<const float4*>(Ws + k * 128)[lane];
        #pragma unroll
        for (int j = 0; j < 8; j++) {
            float xv = xrow[j * 132 + k];
            acc[j][0] = fmaf(xv, w4.x, acc[j][0]);
            acc[j][1] = fmaf(xv, w4.y, acc[j][1]);
            acc[j][2] = fmaf(xv, w4.z, acc[j][2]);
            acc[j][3] = fmaf(xv, w4.w, acc[j][3]);
        }
    }

    #pragma unroll
    for (int j = 0; j < 8; j++) {
        int row = row0 + wrp * 8 + j;
        reinterpret_cast<float4*>(g_hW + (size_t)row * DD)[lane] =
            make_float4(acc[j][0], acc[j][1], acc[j][2], acc[j][3]);
    }
}

// fused: CSR gather + self-loop + bias + ReLU + pooled max/sum/cnt.
// one warp per 8 consecutive nodes (batch sorted -> rare flushes).
__device__ __forceinline__ void pool_flush(int g, int lane, float4 pm, float4 ps, int cl) {
    int base = g * DD + lane * 4;
    atomicMax(&g_pmaxi[base + 0], __float_as_int(pm.x));
    atomicMax(&g_pmaxi[base + 1], __float_as_int(pm.y));
    atomicMax(&g_pmaxi[base + 2], __float_as_int(pm.z));
    atomicMax(&g_pmaxi[base + 3], __float_as_int(pm.w));
    red_add_v4(&g_psum[base], ps.x, ps.y, ps.z, ps.w);
    if (lane == 0) red_add_f32(&g_cnt[g], (float)cl);
}

__global__ void k_gather_pool(const float* __restrict__ bias,
                              const int* __restrict__ batchv) {
    int warp = (blockIdx.x * blockDim.x + threadIdx.x) >> 5;
    if (warp >= NN / 8) return;
    const int lane = threadIdx.x & 31;
    const int n0 = warp * 8;

    float4 bia = reinterpret_cast<const float4*>(bias)[lane];
    float4 pm = make_float4(0.f, 0.f, 0.f, 0.f);
    float4 ps = make_float4(0.f, 0.f, 0.f, 0.f);
    int cl = 0;
    int cur_g = batchv[n0];

    #pragma unroll 1
    for (int i = 0; i < 8; i++) {
        int n = n0 + i;
        int g = batchv[n];
        if (g != cur_g) {
            pool_flush(cur_g, lane, pm, ps, cl);
            pm = make_float4(0.f, 0.f, 0.f, 0.f);
            ps = make_float4(0.f, 0.f, 0.f, 0.f);
            cl = 0;
            cur_g = g;
        }
        float dn = g_deg[n];
        float sl = dn * dn;                          // self-loop norm
        float4 h = reinterpret_cast<const float4*>(g_hW + (size_t)n * DD)[lane];
        float4 acc = make_float4(fmaf(h.x, sl, bia.x), fmaf(h.y, sl, bia.y),
                                 fmaf(h.z, sl, bia.z), fmaf(h.w, sl, bia.w));
        int e0 = row_start(n);
        int e1 = row_start(n + 1);
        int e = e0;
        for (; e + 4 <= e1; e += 4) {
            int s0 = g_csrc[e],     s1 = g_csrc[e + 1];
            int s2 = g_csrc[e + 2], s3 = g_csrc[e + 3];
            float w0 = g_cw[e],     w1 = g_cw[e + 1];
            float w2 = g_cw[e + 2], w3 = g_cw[e + 3];
            float4 v0 = reinterpret_cast<const float4*>(g_hW + (size_t)s0 * DD)[lane];
            float4 v1 = reinterpret_cast<const float4*>(g_hW + (size_t)s1 * DD)[lane];
            float4 v2 = reinterpret_cast<const float4*>(g_hW + (size_t)s2 * DD)[lane];
            float4 v3 = reinterpret_cast<const float4*>(g_hW + (size_t)s3 * DD)[lane];
            acc.x = fmaf(v0.x, w0, fmaf(v1.x, w1, fmaf(v2.x, w2, fmaf(v3.x, w3, acc.x))));
            acc.y = fmaf(v0.y, w0, fmaf(v1.y, w1, fmaf(v2.y, w2, fmaf(v3.y, w3, acc.y))));
            acc.z = fmaf(v0.z, w0, fmaf(v1.z, w1, fmaf(v2.z, w2, fmaf(v3.z, w3, acc.z))));
            acc.w = fmaf(v0.w, w0, fmaf(v1.w, w1, fmaf(v2.w, w2, fmaf(v3.w, w3, acc.w))));
        }
        for (; e < e1; e++) {
            int s0 = g_csrc[e];
            float w0 = g_cw[e];
            float4 v0 = reinterpret_cast<const float4*>(g_hW + (size_t)s0 * DD)[lane];
            acc.x = fmaf(v0.x, w0, acc.x);
            acc.y = fmaf(v0.y, w0, acc.y);
            acc.z = fmaf(v0.z, w0, acc.z);
            acc.w = fmaf(v0.w, w0, acc.w);
        }
        // ReLU
        acc.x = fmaxf(acc.x, 0.f); acc.y = fmaxf(acc.y, 0.f);
        acc.z = fmaxf(acc.z, 0.f); acc.w = fmaxf(acc.w, 0.f);
        // pool into registers
        pm.x = fmaxf(pm.x, acc.x); pm.y = fmaxf(pm.y, acc.y);
        pm.z = fmaxf(pm.z, acc.z); pm.w = fmaxf(pm.w, acc.w);
        ps.x += acc.x; ps.y += acc.y; ps.z += acc.z; ps.w += acc.w;
        cl++;
    }
    pool_flush(cur_g, lane, pm, ps, cl);
}

// per-graph MLP: one block (128 threads) per graph runs all three layers
__global__ void k_mlp(const float* __restrict__ rho,
                      const float* __restrict__ w1, const float* __restrict__ b1,
                      const float* __restrict__ w2, const float* __restrict__ b2,
                      const float* __restrict__ w3, const float* __restrict__ b3,
                      float* __restrict__ out) {
    __shared__ float hg[260];
    __shared__ float z1[DD];
    __shared__ float z2[DD];
    const int g = blockIdx.x;
    const int t = threadIdx.x;

    float cnt = g_cnt[g];
    float inv = 1.0f / fmaxf(cnt, 1.0f);
    hg[t] = __int_as_float(g_pmaxi[g * DD + t]);
    hg[DD + t] = g_psum[g * DD + t] * inv;
    if (t == 0) hg[2 * DD] = rho[g];
    __syncthreads();

    float acc = b1[t];
    #pragma unroll 8
    for (int k = 0; k < 2 * DD + 1; k++) acc = fmaf(hg[k], w1[k * DD + t], acc);
    z1[t] = fmaxf(acc, 0.f);
    __syncthreads();

    acc = b2[t];
    #pragma unroll 8
    for (int k = 0; k < DD; k++) acc = fmaf(z1[k], w2[k * DD + t], acc);
    z2[t] = fmaxf(acc, 0.f);
    __syncthreads();

    if (t < DOUT) {
        acc = b3[t];
        #pragma unroll 8
        for (int k = 0; k < DD; k++) acc = fmaf(z2[k], w3[k * DOUT + t], acc);
        out[g * DOUT + t] = acc;
    }
}

// ---------------- launch -----------------------------------------------------
extern "C" void kernel_launch(void* const* d_in, const int* in_sizes, int n_in,
                              void* d_out, int out_size) {
    const float* x      = (const float*)d_in[0];
    const float* ew     = (const float*)d_in[1];
    const float* rho    = (const float*)d_in[2];
    const float* conv_w = (const float*)d_in[3];
    const float* conv_b = (const float*)d_in[4];
    const float* w1     = (const float*)d_in[5];
    const float* b1     = (const float*)d_in[6];
    const float* w2     = (const float*)d_in[7];
    const float* b2     = (const float*)d_in[8];
    const float* w3     = (const float*)d_in[9];
    const float* b3     = (const float*)d_in[10];
    const int*   ei     = (const int*)d_in[11];
    const int*   batchv = (const int*)d_in[12];
    float* out = (float*)d_out;

    const int gemm_smem = (128 * 128 + 64 * 132) * 4;   // 99328 B
    cudaFuncSetAttribute(k_gemm, cudaFuncAttributeMaxDynamicSharedMemorySize, gemm_smem);

    // reset state
    k_init<<<(NN + 255) / 256, 256>>>();
    // degree + histogram
    k_deg<<<(EE + 255) / 256, 256>>>(ei, ew);
    // block scans (scan1 also fuses deg -> rsqrt)
    k_scan1<<<NSCAN, SCAN_BLK>>>();
    k_scan2<<<1, 64>>>();
    // CSR fill with precomputed norms
    k_fill<<<(EE + 255) / 256, 256>>>(ei, ew);
    // hW = x @ conv_w (independent of CSR; runs here on same stream)
    k_gemm<<<NN / 64, 256, gemm_smem>>>(x, conv_w);
    // fused gather + relu + pool
    k_gather_pool<<<(NN / 8 * 32 + 255) / 256, 256>>>(conv_b, batchv);
    // MLP head
    k_mlp<<<GG, DD>>>(rho, w1, b1, w2, b2, w3, b3, out);
}